// round 3
// baseline (speedup 1.0000x reference)
#include <cuda_runtime.h>
#include <math.h>

// Problem dims
#define BB 4
#define SS 2048
#define EE 768
#define HH 3
#define HD 256
#define BH (BB*HH)        // 12

// Scratch (device globals; no allocation allowed)
__device__ float g_Q[(size_t)BH*SS*HD];
__device__ float g_K[(size_t)BH*SS*HD];
__device__ float g_V[(size_t)BH*SS*HD];
__device__ float g_Hd[(size_t)BH*SS*HD];
__device__ float g_Sc[(size_t)BH*SS*SS];   // 201 MB score/prob buffer

// ---------------------------------------------------------------------------
// Kernel 1: QKV projections.  grid = (4, 32, 36): z = t*12 + b*3 + h
// C[2048x256] = X[b][2048x768] @ W[h][768x256]
// ---------------------------------------------------------------------------
__global__ __launch_bounds__(256) void proj_kernel(
    const float* __restrict__ Xk, const float* __restrict__ Xv, const float* __restrict__ Xq,
    const float* __restrict__ Wk, const float* __restrict__ Wv, const float* __restrict__ Wq)
{
    int z  = blockIdx.z;
    int t  = z / BH;
    int bh = z % BH;
    int b  = bh / HH, h = bh % HH;

    const float* X = (t == 0) ? Xk : (t == 1) ? Xv : Xq;
    const float* W = (t == 0) ? Wk : (t == 1) ? Wv : Wq;
    float*     Out = (t == 0) ? g_K : (t == 1) ? g_V : g_Q;

    __shared__ float As[64][16];
    __shared__ float Bs[16][64];

    int tid = threadIdx.x;
    int m0 = blockIdx.y * 64, n0 = blockIdx.x * 64;
    int ty = tid / 16, tx = tid % 16;
    int ar = tid >> 2, ac = (tid & 3) * 4;
    int br = tid >> 4, bc = (tid & 15) * 4;

    const float* Xbase = X + (size_t)b * SS * EE + (size_t)m0 * EE;
    const float* Wbase = W + (size_t)h * EE * HD;

    float acc[4][4] = {};

    for (int kk = 0; kk < EE; kk += 16) {
        *(float4*)&As[ar][ac] = *(const float4*)&Xbase[(size_t)ar * EE + kk + ac];
        *(float4*)&Bs[br][bc] = *(const float4*)&Wbase[(size_t)(kk + br) * HD + n0 + bc];
        __syncthreads();
        #pragma unroll
        for (int k = 0; k < 16; k++) {
            float a0 = As[ty*4+0][k], a1 = As[ty*4+1][k];
            float a2 = As[ty*4+2][k], a3 = As[ty*4+3][k];
            float4 bv = *(float4*)&Bs[k][tx*4];
            acc[0][0] += a0*bv.x; acc[0][1] += a0*bv.y; acc[0][2] += a0*bv.z; acc[0][3] += a0*bv.w;
            acc[1][0] += a1*bv.x; acc[1][1] += a1*bv.y; acc[1][2] += a1*bv.z; acc[1][3] += a1*bv.w;
            acc[2][0] += a2*bv.x; acc[2][1] += a2*bv.y; acc[2][2] += a2*bv.z; acc[2][3] += a2*bv.w;
            acc[3][0] += a3*bv.x; acc[3][1] += a3*bv.y; acc[3][2] += a3*bv.z; acc[3][3] += a3*bv.w;
        }
        __syncthreads();
    }

    float* Obase = Out + ((size_t)bh * SS + m0) * HD + n0;
    #pragma unroll
    for (int i = 0; i < 4; i++) {
        float4 v = make_float4(acc[i][0], acc[i][1], acc[i][2], acc[i][3]);
        *(float4*)&Obase[(size_t)(ty*4 + i) * HD + tx*4] = v;
    }
}

// ---------------------------------------------------------------------------
// Kernel 2: causal scores S = Q K^T / sqrt(S).  grid = (32, 32, 12)
// Skip tiles strictly above the diagonal.
// ---------------------------------------------------------------------------
__global__ __launch_bounds__(256) void score_kernel()
{
    int bh = blockIdx.z;
    int mt = blockIdx.y, nt = blockIdx.x;
    if (nt > mt) return;

    const float* Q = g_Q + (size_t)bh * SS * HD;
    const float* K = g_K + (size_t)bh * SS * HD;
    float*      Sp = g_Sc + (size_t)bh * SS * SS;

    __shared__ float As[64][16];
    __shared__ float Ks[64][17];   // padded to soften bank conflicts

    int tid = threadIdx.x;
    int m0 = mt * 64, n0 = nt * 64;
    int ty = tid / 16, tx = tid % 16;
    int ar = tid >> 2, ac = (tid & 3) * 4;

    float acc[4][4] = {};

    for (int kk = 0; kk < HD; kk += 16) {
        *(float4*)&As[ar][ac] = *(const float4*)&Q[(size_t)(m0 + ar) * HD + kk + ac];
        float4 kv = *(const float4*)&K[(size_t)(n0 + ar) * HD + kk + ac];
        Ks[ar][ac+0] = kv.x; Ks[ar][ac+1] = kv.y; Ks[ar][ac+2] = kv.z; Ks[ar][ac+3] = kv.w;
        __syncthreads();
        #pragma unroll
        for (int k = 0; k < 16; k++) {
            float a[4], bb[4];
            #pragma unroll
            for (int i = 0; i < 4; i++) a[i]  = As[ty*4+i][k];
            #pragma unroll
            for (int j = 0; j < 4; j++) bb[j] = Ks[tx*4+j][k];
            #pragma unroll
            for (int i = 0; i < 4; i++)
                #pragma unroll
                for (int j = 0; j < 4; j++)
                    acc[i][j] += a[i] * bb[j];
        }
        __syncthreads();
    }

    const float inv_scale = 1.0f / sqrtf((float)SS);
    #pragma unroll
    for (int i = 0; i < 4; i++) {
        int gi = m0 + ty*4 + i;
        #pragma unroll
        for (int j = 0; j < 4; j++) {
            int gj = n0 + tx*4 + j;
            float v = (gj > gi) ? -3.0e38f : acc[i][j] * inv_scale;
            Sp[(size_t)gi * SS + gj] = v;
        }
    }
}

// ---------------------------------------------------------------------------
// Kernel 3: warp-per-row causal softmax.  Zero-fills [row+1, ceil64(row+1))
// so the PV GEMM can include the full diagonal tile.
// ---------------------------------------------------------------------------
__global__ __launch_bounds__(256) void softmax_kernel()
{
    int gwarp = (blockIdx.x * blockDim.x + threadIdx.x) >> 5;
    int lane  = threadIdx.x & 31;
    if (gwarp >= BH * SS) return;

    int bh = gwarp / SS;
    int r  = gwarp % SS;
    float* sp = g_Sc + (size_t)bh * SS * SS + (size_t)r * SS;
    int n = r + 1;

    float mx = -3.0e38f;
    for (int j = lane; j < n; j += 32) mx = fmaxf(mx, sp[j]);
    #pragma unroll
    for (int o = 16; o; o >>= 1) mx = fmaxf(mx, __shfl_xor_sync(0xffffffffu, mx, o));

    float sum = 0.f;
    for (int j = lane; j < n; j += 32) sum += __expf(sp[j] - mx);
    #pragma unroll
    for (int o = 16; o; o >>= 1) sum += __shfl_xor_sync(0xffffffffu, sum, o);

    float inv = 1.0f / sum;
    for (int j = lane; j < n; j += 32) sp[j] = __expf(sp[j] - mx) * inv;

    int nceil = ((n + 63) & ~63);
    for (int j = n + lane; j < nceil; j += 32) sp[j] = 0.f;
}

// ---------------------------------------------------------------------------
// Kernel 4: O = P @ V with causal K-bound.  grid = (4, 32, 12)
// ---------------------------------------------------------------------------
__global__ __launch_bounds__(256) void av_kernel()
{
    int bh = blockIdx.z;
    int mt = blockIdx.y, nt = blockIdx.x;

    const float* P = g_Sc + (size_t)bh * SS * SS;
    const float* V = g_V  + (size_t)bh * SS * HD;
    float*       O = g_Hd + (size_t)bh * SS * HD;

    __shared__ float As[64][16];
    __shared__ float Bs[16][64];

    int tid = threadIdx.x;
    int m0 = mt * 64, n0 = nt * 64;
    int ty = tid / 16, tx = tid % 16;
    int ar = tid >> 2, ac = (tid & 3) * 4;
    int br = tid >> 4, bc = (tid & 15) * 4;

    int kmax = (mt + 1) * 64;
    float acc[4][4] = {};

    for (int kk = 0; kk < kmax; kk += 16) {
        *(float4*)&As[ar][ac] = *(const float4*)&P[(size_t)(m0 + ar) * SS + kk + ac];
        *(float4*)&Bs[br][bc] = *(const float4*)&V[(size_t)(kk + br) * HD + n0 + bc];
        __syncthreads();
        #pragma unroll
        for (int k = 0; k < 16; k++) {
            float a0 = As[ty*4+0][k], a1 = As[ty*4+1][k];
            float a2 = As[ty*4+2][k], a3 = As[ty*4+3][k];
            float4 bv = *(float4*)&Bs[k][tx*4];
            acc[0][0] += a0*bv.x; acc[0][1] += a0*bv.y; acc[0][2] += a0*bv.z; acc[0][3] += a0*bv.w;
            acc[1][0] += a1*bv.x; acc[1][1] += a1*bv.y; acc[1][2] += a1*bv.z; acc[1][3] += a1*bv.w;
            acc[2][0] += a2*bv.x; acc[2][1] += a2*bv.y; acc[2][2] += a2*bv.z; acc[2][3] += a2*bv.w;
            acc[3][0] += a3*bv.x; acc[3][1] += a3*bv.y; acc[3][2] += a3*bv.z; acc[3][3] += a3*bv.w;
        }
        __syncthreads();
    }

    float* Obase = O + ((size_t)m0) * HD + n0;
    #pragma unroll
    for (int i = 0; i < 4; i++) {
        float4 v = make_float4(acc[i][0], acc[i][1], acc[i][2], acc[i][3]);
        *(float4*)&Obase[(size_t)(ty*4 + i) * HD + tx*4] = v;
    }
}

// ---------------------------------------------------------------------------
// Kernel 5: Y = concat(heads) @ Wo + bo.  grid = (12, 128)
// M = B*S = 8192, N = 768, K = 768 (gathered from g_Hd head layout)
// ---------------------------------------------------------------------------
__global__ __launch_bounds__(256) void outproj_kernel(
    const float* __restrict__ Wo, const float* __restrict__ bo, float* __restrict__ Y)
{
    __shared__ float As[64][16];
    __shared__ float Bs[16][64];

    int tid = threadIdx.x;
    int m0 = blockIdx.y * 64, n0 = blockIdx.x * 64;
    int ty = tid / 16, tx = tid % 16;
    int ar = tid >> 2, ac = (tid & 3) * 4;
    int br = tid >> 4, bc = (tid & 15) * 4;

    // 64-row tile stays inside one batch (2048 % 64 == 0)
    int b  = m0 / SS;
    int q0 = m0 % SS;

    float acc[4][4] = {};

    for (int kk = 0; kk < EE; kk += 16) {
        int h = kk / HD;                 // head for this k-tile (16 < 256, no straddle)
        int f = kk % HD;
        const float* Abase = g_Hd + (((size_t)(b * HH + h)) * SS + q0) * HD + f;
        *(float4*)&As[ar][ac] = *(const float4*)&Abase[(size_t)ar * HD + ac];
        *(float4*)&Bs[br][bc] = *(const float4*)&Wo[(size_t)(kk + br) * EE + n0 + bc];
        __syncthreads();
        #pragma unroll
        for (int k = 0; k < 16; k++) {
            float a0 = As[ty*4+0][k], a1 = As[ty*4+1][k];
            float a2 = As[ty*4+2][k], a3 = As[ty*4+3][k];
            float4 bv = *(float4*)&Bs[k][tx*4];
            acc[0][0] += a0*bv.x; acc[0][1] += a0*bv.y; acc[0][2] += a0*bv.z; acc[0][3] += a0*bv.w;
            acc[1][0] += a1*bv.x; acc[1][1] += a1*bv.y; acc[1][2] += a1*bv.z; acc[1][3] += a1*bv.w;
            acc[2][0] += a2*bv.x; acc[2][1] += a2*bv.y; acc[2][2] += a2*bv.z; acc[2][3] += a2*bv.w;
            acc[3][0] += a3*bv.x; acc[3][1] += a3*bv.y; acc[3][2] += a3*bv.z; acc[3][3] += a3*bv.w;
        }
        __syncthreads();
    }

    float4 bias = *(const float4*)&bo[n0 + tx*4];
    #pragma unroll
    for (int i = 0; i < 4; i++) {
        float4 v = make_float4(acc[i][0] + bias.x, acc[i][1] + bias.y,
                               acc[i][2] + bias.z, acc[i][3] + bias.w);
        *(float4*)&Y[(size_t)(m0 + ty*4 + i) * EE + n0 + tx*4] = v;
    }
}

// ---------------------------------------------------------------------------
extern "C" void kernel_launch(void* const* d_in, const int* in_sizes, int n_in,
                              void* d_out, int out_size)
{
    const float* Xk = (const float*)d_in[0];
    const float* Xv = (const float*)d_in[1];
    const float* Xq = (const float*)d_in[2];
    const float* Wk = (const float*)d_in[3];
    const float* Wv = (const float*)d_in[4];
    const float* Wq = (const float*)d_in[5];
    const float* Wo = (const float*)d_in[6];
    const float* bo = (const float*)d_in[7];
    float* out = (float*)d_out;

    proj_kernel<<<dim3(HD/64, SS/64, 3*BH), 256>>>(Xk, Xv, Xq, Wk, Wv, Wq);
    score_kernel<<<dim3(SS/64, SS/64, BH), 256>>>();
    softmax_kernel<<<(BH*SS + 7) / 8, 256>>>();
    av_kernel<<<dim3(HD/64, SS/64, BH), 256>>>();
    outproj_kernel<<<dim3(EE/64, (BB*SS)/64, 1), 256>>>(Wo, bo, out);
}